// round 17
// baseline (speedup 1.0000x reference)
#include <cuda_runtime.h>
#include <cuda_bf16.h>

// ---------------------------------------------------------------------------
// Static geometry:
//   s0: t=8,  32x32 -> tokens [0,8192)      pe2d rows [0,1024)
//   s1: t=16, 16x16 -> tokens [8192,12288)  pe2d rows [1024,1280)
//   s2: t=4,  48x48 -> tokens [12288,21504) pe2d rows [1280,3584)
//   s3: t=1,  64x64 -> tokens [21504,25600) pe = weight rows (independent of prep)
// ---------------------------------------------------------------------------
#define DIM      1280
#define D4       320
#define NROWS_W  96
#define PE_ROWS  3584
#define TOKENS   25600
#define TPB      8          // tokens per add-block (hw & boundaries all % 8 == 0)
#define BAND     40

__device__ float g_tmpW[64 * NROWS_W * DIM];   // [i][c][d]
__device__ float g_pe2d[PE_ROWS * DIM];

// --------------------------- tap-window geometry ---------------------------
__host__ __device__ constexpr int cdiv_ceil(int n, int d) {
    return (n >= 0) ? (n + d - 1) / d : -((-n) / d);
}
__host__ __device__ constexpr int iclamp(int v, int lo, int hi) {
    return v < lo ? lo : (v > hi ? hi : v);
}
__host__ __device__ constexpr int rowStart(int g) {
    return (g < 32) ? iclamp(2 * g - 3, 0, 56)
         : (g < 48) ? iclamp(4 * (g - 32) - 6, 0, 48)
                    : iclamp(cdiv_ceil(8 * (g - 48) - 15, 6), 0, 58);
}
__host__ __device__ constexpr int rowWidth(int g) {
    return (g < 32) ? 8 : (g < 48) ? 16 : 6;
}
__host__ __device__ constexpr bool inGroup(int g, int z) {
    return z == 0 ? (rowStart(g) <= 24) : (rowStart(g) >= 25);
}
__host__ __device__ constexpr int bandBase(int z) { return z * 24; }

// ------------------------ compile-time weight table ------------------------
constexpr double c_abs(double x) { return x < 0.0 ? -x : x; }
constexpr double keys_cubic_c(double x) {
    return (x >= 2.0) ? 0.0
         : (x >= 1.0) ? ((-0.5 * x + 2.5) * x - 4.0) * x + 2.0
                      : ((1.5 * x - 2.5) * x) * x + 1.0;
}

struct WTable { float w[NROWS_W][16]; };

constexpr WTable make_wtable() {
    WTable t{};
    for (int o = 0; o < NROWS_W; o++) {
        int outsz = (o < 32) ? 32 : (o < 48) ? 16 : 48;
        int base  = (o < 32) ? 0  : (o < 48) ? 32 : 48;
        int r = o - base;
        double inv_scale = 64.0 / (double)outsz;
        double ks_inv    = (double)outsz * (1.0 / 64.0);
        double f = ((double)r + 0.5) * inv_scale - 0.5;
        int start = rowStart(o);
        double wv[16] = {};
        double wsum = 0.0;
        for (int k = 0; k < 16; k++) {
            int i = start + k;
            double w = (i < 64) ? keys_cubic_c(c_abs(f - (double)i) * ks_inv) : 0.0;
            wv[k] = w;
            wsum += w;
        }
        for (int k = 0; k < 16; k++)
            t.w[o][k] = (float)(wv[k] / wsum);
    }
    return t;
}

constexpr WTable WT = make_wtable();

// -------------------- full-window emitters (passW) -------------------------
template<int G, int K, bool Done>
struct Tap {
    static __device__ __forceinline__ float run(const float (&v)[64], float acc) {
        constexpr float wk = WT.w[G][K];
        constexpr int   st = rowStart(G);
        acc = fmaf(wk, v[st + K], acc);
        return Tap<G, K + 1, (K + 1 >= rowWidth(G))>::run(v, acc);
    }
};
template<int G, int K>
struct Tap<G, K, true> {
    static __device__ __forceinline__ float run(const float (&)[64], float acc) { return acc; }
};

template<int C, bool Done>
struct WCol {
    static __device__ __forceinline__ void run(const float (&v)[64],
                                               float* __restrict__ outp) {
        outp[(size_t)C * DIM] = Tap<C, 0, false>::run(v, 0.f);
        WCol<C + 1, (C + 1 >= NROWS_W)>::run(v, outp);
    }
};
template<int C>
struct WCol<C, true> {
    static __device__ __forceinline__ void run(const float (&)[64], float*) {}
};

// --------------------- banded emitters (passH) -----------------------------
template<int G, int K, int BASE, bool Done>
struct TapB {
    static __device__ __forceinline__ float run(const float (&v)[BAND], float acc) {
        constexpr float wk = WT.w[G][K];
        constexpr int   ix = rowStart(G) - BASE + K;
        acc = fmaf(wk, v[ix], acc);
        return TapB<G, K + 1, BASE, (K + 1 >= rowWidth(G))>::run(v, acc);
    }
};
template<int G, int K, int BASE>
struct TapB<G, K, BASE, true> {
    static __device__ __forceinline__ float run(const float (&)[BAND], float acc) { return acc; }
};

template<int GBASE, int WS, int R, int Z, bool DoEmit>
struct HEmit {
    static __device__ __forceinline__ void run(const float (&v)[BAND],
                                               float* __restrict__ outp) {
        outp[(size_t)(R * WS) * DIM] = TapB<GBASE + R, 0, bandBase(Z), false>::run(v, 0.f);
    }
};
template<int GBASE, int WS, int R, int Z>
struct HEmit<GBASE, WS, R, Z, false> {
    static __device__ __forceinline__ void run(const float (&)[BAND], float*) {}
};

template<int GBASE, int RCNT, int WS, int R, int Z, bool Done>
struct HRowZ {
    static __device__ __forceinline__ void run(const float (&v)[BAND],
                                               float* __restrict__ outp) {
        HEmit<GBASE, WS, R, Z, inGroup(GBASE + R, Z)>::run(v, outp);
        HRowZ<GBASE, RCNT, WS, R + 1, Z, (R + 1 >= RCNT)>::run(v, outp);
    }
};
template<int GBASE, int RCNT, int WS, int R, int Z>
struct HRowZ<GBASE, RCNT, WS, R, Z, true> {
    static __device__ __forceinline__ void run(const float (&)[BAND], float*) {}
};

// ---------------------------------------------------------------------------
// K1: passW. __launch_bounds__(128, 4) raises the register cap to 128/thread
// so v[64] is truly register-resident -> 64-deep front-batched LDG MLP.
// ---------------------------------------------------------------------------
__global__ __launch_bounds__(128, 4) void passW_kernel(const float* __restrict__ weight) {
#if __CUDA_ARCH__ >= 900
    cudaTriggerProgrammaticLaunchCompletion();
#endif
    int i  = blockIdx.x;
    int d0 = blockIdx.y * 128;
    int tid = threadIdx.x;

    float v[64];
    const float* wrow = weight + (size_t)(i * 64) * DIM + d0 + tid;
    #pragma unroll
    for (int j = 0; j < 64; j++)
        v[j] = wrow[(size_t)j * DIM];

    float* outp = g_tmpW + (size_t)i * NROWS_W * DIM + d0 + tid;
    WCol<0, false>::run(v, outp);
}

// ---------------------------------------------------------------------------
// K2 (PDL secondary): blocks [0,1024)   = idadd (independent, overlaps K1)
//                     blocks [1024,2064) = passH (gridDepSync, banded).
// __launch_bounds__(256, 2) -> reg cap 128 so v[40] stays resident.
// ---------------------------------------------------------------------------
__global__ __launch_bounds__(256, 2) void fused_idadd_passH_kernel(
        const float4* __restrict__ x,
        const float*  __restrict__ weight,
        float4* __restrict__ out) {
#if __CUDA_ARCH__ >= 900
    cudaTriggerProgrammaticLaunchCompletion();
#endif
    int b = blockIdx.x;

    if (b < 1024) {
        // ---- identity add, 4 tokens = 1280 contiguous float4 per block ----
        int u = b * 4;
        const float4* w4 = (const float4*)weight;
        size_t xb = (size_t)(21504 + u) * D4;
        size_t wb = (size_t)u * D4;
        int tid = threadIdx.x;
        #pragma unroll
        for (int j = 0; j < 5; j++) {                     // 5*256 = 1280
            int e = j * 256 + tid;
            float4 a  = __ldcs(&x[xb + e]);
            float4 pe = w4[wb + e];
            float4 r;
            r.x = a.x + pe.x; r.y = a.y + pe.y;
            r.z = a.z + pe.z; r.w = a.w + pe.w;
            __stcs(&out[xb + e], r);
        }
        return;
    }

#if __CUDA_ARCH__ >= 900
    cudaGridDependencySynchronize();                      // tmpW must be complete
#endif
    int bb = b - 1024;
    int c  = bb / 10;
    int d0 = (bb % 10) * 128;
    int tid = threadIdx.x & 127;
    int z   = threadIdx.x >> 7;

    float v[BAND];
    const float* src = g_tmpW + (size_t)c * DIM
                     + (size_t)(z * 24) * (NROWS_W * DIM) + d0 + tid;
    #pragma unroll
    for (int i = 0; i < BAND; i++)
        v[i] = src[(size_t)i * (NROWS_W * DIM)];

    if (c < 32) {
        float* outp = g_pe2d + (size_t)c * DIM + d0 + tid;
        if (z == 0) HRowZ<0, 32, 32, 0, 0, false>::run(v, outp);
        else        HRowZ<0, 32, 32, 0, 1, false>::run(v, outp);
    } else if (c < 48) {
        float* outp = g_pe2d + (size_t)(1024 + (c - 32)) * DIM + d0 + tid;
        if (z == 0) HRowZ<32, 16, 16, 0, 0, false>::run(v, outp);
        else        HRowZ<32, 16, 16, 0, 1, false>::run(v, outp);
    } else {
        float* outp = g_pe2d + (size_t)(1280 + (c - 48)) * DIM + d0 + tid;
        if (z == 0) HRowZ<48, 48, 48, 0, 0, false>::run(v, outp);
        else        HRowZ<48, 48, 48, 0, 1, false>::run(v, outp);
    }
}

// ---------------------------------------------------------------------------
// K3 (PDL secondary): pe-add for s0/s1/s2, TPB=8 (frame still block-uniform:
// all hw and boundaries divisible by 8). x-preamble before gridDepSync.
// ---------------------------------------------------------------------------
__global__ __launch_bounds__(320, 2) void add_kernel(const float4* __restrict__ x,
                                                     const float4* __restrict__ tw,
                                                     float4* __restrict__ out) {
    int t0 = blockIdx.x * TPB;
    int d4 = threadIdx.x;

    size_t base = (size_t)t0 * D4 + d4;
    float4 a[TPB];
    #pragma unroll
    for (int j = 0; j < TPB; j++) a[j] = __ldcs(&x[base + (size_t)j * D4]);

#if __CUDA_ARCH__ >= 900
    cudaGridDependencySynchronize();                      // pe2d must be complete
#endif

    const float4* pe0;
    int frame;
    if (t0 < 8192) {                        // s0: t=8, 32x32
        frame = t0 >> 10;
        pe0 = (const float4*)g_pe2d + (size_t)(t0 & 1023) * D4;
    } else if (t0 < 12288) {                // s1: t=16, 16x16
        int u = t0 - 8192;
        frame = u >> 8;
        pe0 = (const float4*)g_pe2d + (size_t)(1024 + (u & 255)) * D4;
    } else {                                // s2: t=4, 48x48
        int u = t0 - 12288;
        frame = u / 2304;
        pe0 = (const float4*)g_pe2d + (size_t)(1280 + (u - frame * 2304)) * D4;
    }

    float4 t = tw[(size_t)frame * D4 + d4];

    #pragma unroll
    for (int j = 0; j < TPB; j++) {
        float4 bpe = pe0[(size_t)j * D4 + d4];
        float4 r;
        r.x = a[j].x + bpe.x + t.x;
        r.y = a[j].y + bpe.y + t.y;
        r.z = a[j].z + bpe.z + t.z;
        r.w = a[j].w + bpe.w + t.w;
        __stcs(&out[base + (size_t)j * D4], r);
    }
}

// ---------------------------------------------------------------------------
static void launch_pdl(const void* func, dim3 grid, dim3 block, void** args) {
    cudaLaunchConfig_t cfg = {};
    cfg.gridDim = grid;
    cfg.blockDim = block;
    cfg.dynamicSmemBytes = 0;
    cfg.stream = 0;
    cudaLaunchAttribute attr[1];
    attr[0].id = cudaLaunchAttributeProgrammaticStreamSerialization;
    attr[0].val.programmaticStreamSerializationAllowed = 1;
    cfg.attrs = attr;
    cfg.numAttrs = 1;
    cudaLaunchKernelExC(&cfg, func, args);
}

extern "C" void kernel_launch(void* const* d_in, const int* in_sizes, int n_in,
                              void* d_out, int out_size) {
    const float* x      = (const float*)d_in[0];
    const float* weight = (const float*)d_in[1];
    const float* tw     = (const float*)d_in[2];
    float* out = (float*)d_out;

    // K1: passW (primary; triggers early)
    passW_kernel<<<dim3(64, 10), 128>>>(weight);

    // K2: idadd (independent) + passH (gridDepSync), PDL-overlapped with K1
    {
        const float4* xa = (const float4*)x;
        float4* oa = (float4*)out;
        void* args[] = { (void*)&xa, (void*)&weight, (void*)&oa };
        launch_pdl((const void*)fused_idadd_passH_kernel,
                   dim3(1024 + 960), dim3(256), args);
    }

    // K3: pe-add with x-preamble, PDL-overlapped with K2
    {
        const float4* xa = (const float4*)x;
        const float4* twa = (const float4*)tw;
        float4* oa = (float4*)out;
        void* args[] = { (void*)&xa, (void*)&twa, (void*)&oa };
        launch_pdl((const void*)add_kernel, dim3(21504 / TPB), dim3(320), args);
    }
}